// round 6
// baseline (speedup 1.0000x reference)
#include <cuda_runtime.h>
#include <cuda_bf16.h>

#define DD 128
#define HH 512
#define WW 512
#define NVOX (DD*HH*WW)          // 33,554,432
#define NF4  (NVOX/4)            // 8,388,608
#define THRESH 0.997f
#define KPK 131072
#define NB  65536
#define CAND_CAP (1<<18)         // 262144

// ---------------- device scratch (static; no allocation) ----------------
__device__ unsigned g_hist[NB];
__device__ unsigned g_cur[NB];
__device__ unsigned g_off[NB];
__device__ unsigned g_ncand;
__device__ unsigned g_total;
__device__ unsigned g_cand_idx[CAND_CAP];
__device__ unsigned g_cand_bucket[CAND_CAP];
__device__ unsigned g_sorted_idx[KPK];

// ---------------- kernel 0: zero scratch ----------------
__global__ void k_zero() {
    unsigned i = blockIdx.x * blockDim.x + threadIdx.x;
    if (i < NB) { g_hist[i] = 0u; g_cur[i] = 0u; }
    if (i == 0) { g_ncand = 0u; g_total = 0u; }
}

// ---------------- kernel 1: scan volume, compact candidates (v > THRESH) ----------------
// 4096 blocks x 256 threads, each block owns 2048 float4 = 8192 voxels.
__global__ void k_detect(const float* __restrict__ vol) {
    __shared__ unsigned s_cand[1024];
    __shared__ unsigned s_cnt, s_base;
    if (threadIdx.x == 0) s_cnt = 0u;
    __syncthreads();

    const float4* v4 = (const float4*)vol;
    unsigned tile = blockIdx.x * 2048u;
#pragma unroll
    for (int j = 0; j < 8; j++) {
        unsigned i = tile + j * 256u + threadIdx.x;
        float4 f = v4[i];
        unsigned base = i * 4u;
        if (f.x > THRESH) { unsigned p = atomicAdd(&s_cnt, 1u); if (p < 1024u) s_cand[p] = base + 0u; }
        if (f.y > THRESH) { unsigned p = atomicAdd(&s_cnt, 1u); if (p < 1024u) s_cand[p] = base + 1u; }
        if (f.z > THRESH) { unsigned p = atomicAdd(&s_cnt, 1u); if (p < 1024u) s_cand[p] = base + 2u; }
        if (f.w > THRESH) { unsigned p = atomicAdd(&s_cnt, 1u); if (p < 1024u) s_cand[p] = base + 3u; }
    }
    __syncthreads();
    unsigned cnt = min(s_cnt, 1024u);
    if (threadIdx.x == 0) s_base = atomicAdd(&g_ncand, cnt);
    __syncthreads();
    for (unsigned j = threadIdx.x; j < cnt; j += blockDim.x) {
        unsigned p = s_base + j;
        if (p < CAND_CAP) g_cand_idx[p] = s_cand[j];
    }
}

// ---------------- kernel 2: verify 7^3 local max, histogram by value bucket ----------------
__global__ void k_verify(const float* __restrict__ vol) {
    unsigned i = blockIdx.x * blockDim.x + threadIdx.x;
    unsigned n = min(g_ncand, (unsigned)CAND_CAP);
    if (i >= n) return;
    unsigned idx = g_cand_idx[i];
    int z = idx >> 18, y = (idx >> 9) & 511, x = idx & 511;
    float v = vol[idx];
    int z0 = max(z - 3, 0), z1 = min(z + 3, DD - 1);
    int y0 = max(y - 3, 0), y1 = min(y + 3, HH - 1);
    int x0 = max(x - 3, 0), x1 = min(x + 3, WW - 1);
    bool peak = true;
    for (int zz = z0; zz <= z1 && peak; zz++) {
        const float* pz = vol + ((unsigned)zz << 18);
        for (int yy = y0; yy <= y1 && peak; yy++) {
            const float* pr = pz + ((unsigned)yy << 9);
            for (int xx = x0; xx <= x1; xx++) {
                if (pr[xx] > v) { peak = false; break; }
            }
        }
    }
    unsigned bucket = 0xFFFFFFFFu;
    if (peak) {
        bucket = __float_as_uint(v) & 0xFFFFu;   // all values in (0.997,1): top 16 bits = 0x3F7F
        atomicAdd(&g_hist[bucket], 1u);
    }
    g_cand_bucket[i] = bucket;
}

// ---------------- kernel 3: suffix (descending) exclusive scan over 65536 buckets ----------------
// one block, 1024 threads, 64 buckets per thread.
__global__ void k_scan() {
    __shared__ unsigned s[1024];
    int t = threadIdx.x;
    int base = t * 64;
    unsigned sum = 0;
    for (int i = 0; i < 64; i++) sum += g_hist[base + i];
    s[t] = sum;
    __syncthreads();
    // inclusive suffix scan (Hillis-Steele)
    for (int d = 1; d < 1024; d <<= 1) {
        unsigned add = (t + d < 1024) ? s[t + d] : 0u;
        __syncthreads();
        s[t] += add;
        __syncthreads();
    }
    unsigned run = s[t] - sum;   // strictly-after suffix for this chunk
    for (int i = 63; i >= 0; --i) {
        unsigned h = g_hist[base + i];
        g_off[base + i] = run;
        run += h;
    }
    if (t == 0) g_total = min(s[0], (unsigned)KPK);
}

// ---------------- kernel 4: scatter peaks into descending-value order ----------------
__global__ void k_scatter() {
    unsigned i = blockIdx.x * blockDim.x + threadIdx.x;
    unsigned n = min(g_ncand, (unsigned)CAND_CAP);
    if (i >= n) return;
    unsigned b = g_cand_bucket[i];
    if (b == 0xFFFFFFFFu) return;
    unsigned pos = g_off[b] + atomicAdd(&g_cur[b], 1u);
    if (pos < (unsigned)KPK) g_sorted_idx[pos] = g_cand_idx[i];
}

// ---------------- kernel 5: per-bucket index sort (ties = identical value; lower index first) ----------------
__global__ void k_bucket_sort() {
    unsigned b = blockIdx.x * blockDim.x + threadIdx.x;
    if (b >= NB) return;
    unsigned c = g_hist[b];
    if (c < 2u) return;
    unsigned s = g_off[b];
    if (s >= (unsigned)KPK) return;
    if (s + c > (unsigned)KPK) c = (unsigned)KPK - s;
    for (unsigned i = 1; i < c; i++) {
        unsigned key = g_sorted_idx[s + i];
        int j = (int)i - 1;
        while (j >= 0 && g_sorted_idx[s + j] > key) {
            g_sorted_idx[s + j + 1] = g_sorted_idx[s + j];
            j--;
        }
        g_sorted_idx[s + j + 1] = key;
    }
}

// ---------------- kernel 6: centroid refine + write output (1 warp per row) ----------------
__global__ void k_centroid(const float* __restrict__ vol, float* __restrict__ out,
                           float* __restrict__ validOut, int writeValid) {
    unsigned gtid = blockIdx.x * blockDim.x + threadIdx.x;
    unsigned row = gtid >> 5;
    int lane = threadIdx.x & 31;
    if (row >= (unsigned)KPK) return;
    unsigned total = g_total;
    if (row >= total) {
        if (lane == 0) {
            float4 zz4 = make_float4(0.f, 0.f, 0.f, 0.f);
            ((float4*)out)[row] = zz4;
            if (writeValid) validOut[row] = 0.f;
        }
        return;
    }
    unsigned idx = g_sorted_idx[row];
    int z = idx >> 18, y = (idx >> 9) & 511, x = idx & 511;

    float s0 = 0.f, sx = 0.f, sy = 0.f, sz = 0.f;
    for (int q = lane; q < 49; q += 32) {
        int dz = q / 7, dy = q - dz * 7;
        int zz = z + dz - 3, yy = y + dy - 3;
        if ((unsigned)zz < (unsigned)DD && (unsigned)yy < (unsigned)HH) {
            const float* rp = vol + ((unsigned)zz << 18) + ((unsigned)yy << 9);
            float rs0 = 0.f, rsx = 0.f;
#pragma unroll
            for (int dx = 0; dx < 7; dx++) {
                int xx = x + dx - 3;
                float vv = ((unsigned)xx < (unsigned)WW) ? rp[xx] : 0.f;
                rs0 += vv;
                rsx += vv * (float)(dx - 3);
            }
            s0 += rs0;
            sx += rsx;
            sy += rs0 * (float)(dy - 3);
            sz += rs0 * (float)(dz - 3);
        }
    }
#pragma unroll
    for (int o = 16; o; o >>= 1) {
        s0 += __shfl_xor_sync(0xFFFFFFFFu, s0, o);
        sx += __shfl_xor_sync(0xFFFFFFFFu, sx, o);
        sy += __shfl_xor_sync(0xFFFFFFFFu, sy, o);
        sz += __shfl_xor_sync(0xFFFFFFFFu, sz, o);
    }
    if (lane == 0) {
        float val  = vol[idx];
        float inv  = 1.f / s0;
        float xrec = ((float)x + sx * inv - 255.5f) * 0.1f;
        float yrec = ((float)y + sy * inv - 255.5f) * 0.1f;
        float zrec = ((float)z + sz * inv + 0.5f) * 0.02f - 2.0f;
        ((float4*)out)[row] = make_float4(xrec, yrec, zrec, val);
        if (writeValid) validOut[row] = 1.f;
    }
}

// ---------------- launch ----------------
extern "C" void kernel_launch(void* const* d_in, const int* in_sizes, int n_in,
                              void* d_out, int out_size) {
    const float* vol = (const float*)d_in[0];
    float* out = (float*)d_out;
    int writeValid = (out_size >= KPK * 5) ? 1 : 0;
    float* validOut = out + (size_t)KPK * 4;

    k_zero<<<NB / 256, 256>>>();
    k_detect<<<4096, 256>>>(vol);
    k_verify<<<CAND_CAP / 256, 256>>>(vol);
    k_scan<<<1, 1024>>>();
    k_scatter<<<CAND_CAP / 256, 256>>>();
    k_bucket_sort<<<NB / 256, 256>>>();
    k_centroid<<<(KPK * 32) / 256, 256>>>(vol, out, validOut, writeValid);
}

// round 7
// speedup vs baseline: 3.3065x; 3.3065x over previous
#include <cuda_runtime.h>
#include <cuda_bf16.h>

#define DD 128
#define HH 512
#define WW 512
#define NVOX (DD*HH*WW)          // 33,554,432
#define THRESH 0.997f
#define KPK 131072
#define NB  65536
#define NCH 64                   // 64 chunks of 1024 buckets
#define CAND_CAP (1<<18)         // 262144

// ---------------- device scratch (static; no allocation) ----------------
// value-bucket machinery (16 low mantissa bits; all peak values share top 16 bits 0x3F7F)
__device__ unsigned g_hist[NB];
__device__ unsigned g_cur[NB];
__device__ unsigned g_off[NB];
__device__ unsigned b_chunk[NCH];
__device__ unsigned b_csuf[NCH];
// spatial cell machinery (8x8x8 cells -> 16*64*64 = 65536 cells)
__device__ unsigned c_cnt[NB];
__device__ unsigned c_cur[NB];
__device__ unsigned c_off[NB];
__device__ unsigned c_chunk[NCH];
__device__ unsigned c_csuf[NCH];
__device__ uint2    c_data[CAND_CAP];   // (idx, valbits) per candidate, grouped by cell
// candidates / results
__device__ unsigned g_ncand;
__device__ unsigned g_total;
__device__ unsigned g_cand_idx[CAND_CAP];
__device__ unsigned g_cand_bucket[CAND_CAP];
__device__ unsigned g_sorted_idx[KPK];

__device__ __forceinline__ unsigned cell_of(unsigned idx) {
    unsigned z = idx >> 18, y = (idx >> 9) & 511u, x = idx & 511u;
    return ((z >> 3) << 12) | ((y >> 3) << 6) | (x >> 3);
}

// ---------------- kernel 0: zero scratch ----------------
__global__ void k_zero() {
    unsigned i = blockIdx.x * blockDim.x + threadIdx.x;
    if (i < NB) { g_hist[i] = 0u; g_cur[i] = 0u; c_cnt[i] = 0u; c_cur[i] = 0u; }
    if (i == 0) { g_ncand = 0u; g_total = 0u; }
}

// ---------------- kernel 1: scan volume, compact candidates (v > THRESH), count cells ----
__global__ void k_detect(const float* __restrict__ vol) {
    __shared__ unsigned s_cand[1024];
    __shared__ unsigned s_cnt, s_base;
    if (threadIdx.x == 0) s_cnt = 0u;
    __syncthreads();

    const float4* v4 = (const float4*)vol;
    unsigned tile = blockIdx.x * 2048u;
#pragma unroll
    for (int j = 0; j < 8; j++) {
        unsigned i = tile + j * 256u + threadIdx.x;
        float4 f = v4[i];
        unsigned base = i * 4u;
        if (f.x > THRESH) { unsigned p = atomicAdd(&s_cnt, 1u); if (p < 1024u) s_cand[p] = base + 0u; }
        if (f.y > THRESH) { unsigned p = atomicAdd(&s_cnt, 1u); if (p < 1024u) s_cand[p] = base + 1u; }
        if (f.z > THRESH) { unsigned p = atomicAdd(&s_cnt, 1u); if (p < 1024u) s_cand[p] = base + 2u; }
        if (f.w > THRESH) { unsigned p = atomicAdd(&s_cnt, 1u); if (p < 1024u) s_cand[p] = base + 3u; }
    }
    __syncthreads();
    unsigned cnt = min(s_cnt, 1024u);
    if (threadIdx.x == 0) s_base = atomicAdd(&g_ncand, cnt);
    __syncthreads();
    for (unsigned j = threadIdx.x; j < cnt; j += blockDim.x) {
        unsigned p = s_base + j;
        if (p < CAND_CAP) {
            unsigned idx = s_cand[j];
            g_cand_idx[p] = idx;
            atomicAdd(&c_cnt[cell_of(idx)], 1u);   // spread over 65536 addrs: no contention
        }
    }
}

// ---------------- generic hierarchical suffix scan over 65536 counters ----------------
// level 1: 64 blocks x 256 threads; block b scans its 1024-entry chunk (local suffix),
// writing "strictly-after within chunk" offsets and the chunk total.
__global__ void k_scan_blocks(int which) {
    const unsigned* __restrict__ cnt = which ? g_hist : c_cnt;
    unsigned* __restrict__ off   = which ? g_off   : c_off;
    unsigned* __restrict__ chunk = which ? b_chunk : c_chunk;
    __shared__ unsigned s_h[1024];
    __shared__ unsigned s_w[8];
    int t = threadIdx.x;
    unsigned base = blockIdx.x * 1024u;
#pragma unroll
    for (int j = 0; j < 4; j++) s_h[j * 256 + t] = cnt[base + j * 256 + t];
    __syncthreads();
    unsigned h0 = s_h[t*4+0], h1 = s_h[t*4+1], h2 = s_h[t*4+2], h3 = s_h[t*4+3];
    unsigned sum4 = h0 + h1 + h2 + h3;
    unsigned v = sum4;
    int lane = t & 31, w = t >> 5;
#pragma unroll
    for (int d = 1; d < 32; d <<= 1) {
        unsigned o = __shfl_down_sync(0xFFFFFFFFu, v, d);
        if (lane + d < 32) v += o;
    }
    if (lane == 0) s_w[w] = v;     // warp total (inclusive suffix at lane 0)
    __syncthreads();
    unsigned wafter = 0;
    for (int i = w + 1; i < 8; i++) wafter += s_w[i];
    unsigned run = wafter + (v - sum4);    // strictly-after this thread's 4-group, within chunk
    unsigned o3 = run; run += h3;
    unsigned o2 = run; run += h2;
    unsigned o1 = run; run += h1;
    unsigned o0 = run; run += h0;
    off[base + t*4 + 0] = o0;
    off[base + t*4 + 1] = o1;
    off[base + t*4 + 2] = o2;
    off[base + t*4 + 3] = o3;
    if (t == 0) chunk[blockIdx.x] = run;   // chunk total
}

// level 2: one block, 64 threads: csuf[b] = sum of chunk totals strictly after b.
__global__ void k_scan_chunks(int which) {
    __shared__ unsigned s[NCH];
    int t = threadIdx.x;
    unsigned* chunk = which ? b_chunk : c_chunk;
    unsigned* csuf  = which ? b_csuf  : c_csuf;
    s[t] = chunk[t];
    __syncthreads();
    unsigned suf = 0;
    for (int i = t + 1; i < NCH; i++) suf += s[i];
    csuf[t] = suf;
    if (which && t == 0) {
        unsigned tot = suf + s[0];
        g_total = min(tot, (unsigned)KPK);
    }
}

// ---------------- kernel: fill cell lists with (idx, val) records ----------------
__global__ void k_cellfill(const float* __restrict__ vol) {
    unsigned i = blockIdx.x * blockDim.x + threadIdx.x;
    unsigned n = min(g_ncand, (unsigned)CAND_CAP);
    if (i >= n) return;
    unsigned idx = g_cand_idx[i];
    float v = vol[idx];
    unsigned c = cell_of(idx);
    unsigned pos = c_off[c] + c_csuf[c >> 10] + atomicAdd(&c_cur[c], 1u);
    if (pos < CAND_CAP) c_data[pos] = make_uint2(idx, __float_as_uint(v));
}

// ---------------- kernel: verify 7^3 local max using cell lists ----------------
// A defeating neighbor (value > v > 0.997) is itself a candidate, so only
// candidate records in the <=8 overlapping cells need checking.
__global__ void k_verify(const float* __restrict__ vol) {
    unsigned i = blockIdx.x * blockDim.x + threadIdx.x;
    unsigned n = min(g_ncand, (unsigned)CAND_CAP);
    if (i >= n) return;
    unsigned idx = g_cand_idx[i];
    int z = idx >> 18, y = (idx >> 9) & 511, x = idx & 511;
    float v = vol[idx];

    int cz0 = max(z - 3, 0) >> 3, cz1 = min(z + 3, DD - 1) >> 3;
    int cy0 = max(y - 3, 0) >> 3, cy1 = min(y + 3, HH - 1) >> 3;
    int cx0 = max(x - 3, 0) >> 3, cx1 = min(x + 3, WW - 1) >> 3;
    bool peak = true;
    for (int cz = cz0; cz <= cz1 && peak; cz++)
    for (int cy = cy0; cy <= cy1 && peak; cy++)
    for (int cx = cx0; cx <= cx1 && peak; cx++) {
        unsigned c = ((unsigned)cz << 12) | ((unsigned)cy << 6) | (unsigned)cx;
        unsigned cn = c_cnt[c];
        unsigned base = c_off[c] + c_csuf[c >> 10];
        for (unsigned j = 0; j < cn; j++) {
            uint2 r = c_data[base + j];
            if (__uint_as_float(r.y) > v) {
                int rz = r.x >> 18, ry = (r.x >> 9) & 511, rx = r.x & 511;
                if (abs(rz - z) <= 3 && abs(ry - y) <= 3 && abs(rx - x) <= 3) {
                    peak = false; break;
                }
            }
        }
    }
    unsigned bucket = 0xFFFFFFFFu;
    if (peak) {
        bucket = __float_as_uint(v) & 0xFFFFu;   // monotone key: all values share top bits 0x3F7F
        atomicAdd(&g_hist[bucket], 1u);
    }
    g_cand_bucket[i] = bucket;
}

// ---------------- kernel: scatter peaks into descending-value order ----------------
__global__ void k_scatter() {
    unsigned i = blockIdx.x * blockDim.x + threadIdx.x;
    unsigned n = min(g_ncand, (unsigned)CAND_CAP);
    if (i >= n) return;
    unsigned b = g_cand_bucket[i];
    if (b == 0xFFFFFFFFu) return;
    unsigned pos = g_off[b] + b_csuf[b >> 10] + atomicAdd(&g_cur[b], 1u);
    if (pos < (unsigned)KPK) g_sorted_idx[pos] = g_cand_idx[i];
}

// ---------------- kernel: per-bucket index sort (ties: lower index first) ----------------
__global__ void k_bucket_sort() {
    unsigned b = blockIdx.x * blockDim.x + threadIdx.x;
    if (b >= NB) return;
    unsigned c = g_hist[b];
    if (c < 2u) return;
    unsigned s = g_off[b] + b_csuf[b >> 10];
    if (s >= (unsigned)KPK) return;
    if (s + c > (unsigned)KPK) c = (unsigned)KPK - s;
    for (unsigned i = 1; i < c; i++) {
        unsigned key = g_sorted_idx[s + i];
        int j = (int)i - 1;
        while (j >= 0 && g_sorted_idx[s + j] > key) {
            g_sorted_idx[s + j + 1] = g_sorted_idx[s + j];
            j--;
        }
        g_sorted_idx[s + j + 1] = key;
    }
}

// ---------------- kernel: centroid refine + write output (1 warp per row) ----------------
// Vectorized: each 7-element x-run is covered by three aligned float4 loads from
// base a = clamp((x-3)&~3, 0, 500); out-of-window elements are weight-masked
// (matching the reference's zero padding).
__global__ void k_centroid(const float* __restrict__ vol, float* __restrict__ out,
                           float* __restrict__ validOut, int writeValid) {
    unsigned gtid = blockIdx.x * blockDim.x + threadIdx.x;
    unsigned row = gtid >> 5;
    int lane = threadIdx.x & 31;
    if (row >= (unsigned)KPK) return;
    unsigned total = g_total;
    if (row >= total) {
        if (lane == 0) {
            ((float4*)out)[row] = make_float4(0.f, 0.f, 0.f, 0.f);
            if (writeValid) validOut[row] = 0.f;
        }
        return;
    }
    unsigned idx = g_sorted_idx[row];
    int z = idx >> 18, y = (idx >> 9) & 511, x = idx & 511;

    int a = max(x - 3, 0) & ~3;
    if (a > WW - 12) a = WW - 12;        // keep [a, a+12) inside the row

    float s0 = 0.f, sx = 0.f, sy = 0.f, sz = 0.f;
    for (int q = lane; q < 49; q += 32) {
        int dz = q / 7, dy = q - dz * 7;
        int zz = z + dz - 3, yy = y + dy - 3;
        if ((unsigned)zz < (unsigned)DD && (unsigned)yy < (unsigned)HH) {
            const float* rp = vol + ((unsigned)zz << 18) + ((unsigned)yy << 9);
            float4 A = *(const float4*)(rp + a);
            float4 B = *(const float4*)(rp + a + 4);
            float4 C = *(const float4*)(rp + a + 8);
            float vals[12] = {A.x, A.y, A.z, A.w, B.x, B.y, B.z, B.w, C.x, C.y, C.z, C.w};
            float rs0 = 0.f, rsx = 0.f;
#pragma unroll
            for (int e = 0; e < 12; e++) {
                int dx = a + e - x;                       // signed offset from center
                bool in = (dx >= -3) && (dx <= 3);
                float vv = in ? vals[e] : 0.f;
                rs0 += vv;
                rsx += vv * (float)dx;
            }
            s0 += rs0;
            sx += rsx;
            sy += rs0 * (float)(dy - 3);
            sz += rs0 * (float)(dz - 3);
        }
    }
#pragma unroll
    for (int o = 16; o; o >>= 1) {
        s0 += __shfl_xor_sync(0xFFFFFFFFu, s0, o);
        sx += __shfl_xor_sync(0xFFFFFFFFu, sx, o);
        sy += __shfl_xor_sync(0xFFFFFFFFu, sy, o);
        sz += __shfl_xor_sync(0xFFFFFFFFu, sz, o);
    }
    if (lane == 0) {
        float val  = vol[idx];
        float inv  = 1.f / s0;
        float xrec = ((float)x + sx * inv - 255.5f) * 0.1f;
        float yrec = ((float)y + sy * inv - 255.5f) * 0.1f;
        float zrec = ((float)z + sz * inv + 0.5f) * 0.02f - 2.0f;
        ((float4*)out)[row] = make_float4(xrec, yrec, zrec, val);
        if (writeValid) validOut[row] = 1.f;
    }
}

// ---------------- launch ----------------
extern "C" void kernel_launch(void* const* d_in, const int* in_sizes, int n_in,
                              void* d_out, int out_size) {
    const float* vol = (const float*)d_in[0];
    float* out = (float*)d_out;
    int writeValid = (out_size >= KPK * 5) ? 1 : 0;
    float* validOut = out + (size_t)KPK * 4;

    k_zero<<<NB / 256, 256>>>();
    k_detect<<<4096, 256>>>(vol);
    k_scan_blocks<<<NCH, 256>>>(0);       // cell-count suffix scan, level 1
    k_scan_chunks<<<1, NCH>>>(0);         // level 2
    k_cellfill<<<CAND_CAP / 256, 256>>>(vol);
    k_verify<<<CAND_CAP / 256, 256>>>(vol);
    k_scan_blocks<<<NCH, 256>>>(1);       // value-bucket suffix scan, level 1
    k_scan_chunks<<<1, NCH>>>(1);         // level 2 (+ g_total)
    k_scatter<<<CAND_CAP / 256, 256>>>();
    k_bucket_sort<<<NB / 256, 256>>>();
    k_centroid<<<(KPK * 32) / 256, 256>>>(vol, out, validOut, writeValid);
}